// round 11
// baseline (speedup 1.0000x reference)
#include <cuda_runtime.h>

typedef unsigned long long ull;

#define B_TOTAL  4096
#define T_STEPS  512
#define H        64
#define NTHREADS 256     // 8 warps = 4 pairs; pair = {w, w+4}
#define NPAIRS   4
#define JP       8       // batches per pair
#define JO       4       // batches owned (updated) per member warp
#define NB       32      // batches per CTA

// smem layout in ull (8B) units:
//   w0  [32][256] : w0[kp][row] = {W_hh0[row][2kp], W_hh0[row][2kp+1]}   64 KB
//   wc  [64][256] : kp<32 -> W_ih1 pairs, kp>=32 -> W_hh1 pairs         128 KB
//   hb  : per pair: h0[8][32] ull then h1[8][32] ull                     16 KB
//   pad : per pair: [8 j][2 writer-gates][32 lanes] ull gate partials    16 KB
#define W0_ULL   0
#define WC_ULL   (32*256)
#define HB_ULL   (WC_ULL + 64*256)          // 24576
#define PAD_ULL  (HB_ULL + NPAIRS*2*JP*32)  // 26624
#define SMEM_ULLS (PAD_ULL + NPAIRS*JP*2*32)// 28672
#define SMEM_BYTES (SMEM_ULLS * 8)          // 229376 <= 232448

__device__ __forceinline__ ull pack2(float a, float b){
    ull r; asm("mov.b64 %0, {%1, %2};" : "=l"(r) : "f"(a), "f"(b)); return r;
}
__device__ __forceinline__ void fma2(ull &d, ull a, ull b){
    asm("fma.rn.f32x2 %0, %1, %2, %0;" : "+l"(d) : "l"(a), "l"(b));
}
__device__ __forceinline__ float2 unpack2(ull v){
    float lo, hi; asm("mov.b64 {%0, %1}, %2;" : "=f"(lo), "=f"(hi) : "l"(v));
    return make_float2(lo, hi);
}
__device__ __forceinline__ float sum2(ull v){
    float2 p = unpack2(v); return p.x + p.y;
}
__device__ __forceinline__ float sigm(float x){
    float e = __expf(-fabsf(x));
    float s = __fdividef(1.0f, 1.0f + e);
    return (x >= 0.0f) ? s : 1.0f - s;
}
__device__ __forceinline__ float tanh_f(float x){
    float e = __expf(-2.0f * fabsf(x));
    float t = __fdividef(1.0f - e, 1.0f + e);
    return copysignf(t, x);
}

extern __shared__ ull smem[];

// Gate-split GEMM over a 64-deep K block. This member computes ONLY its two
// gates (rows rowoff + {0,64} per k-pair) for all JP batches.
// hb[j*32+kp] = {h_2kp, h_2kp+1}; w[kp*256 + row] = {W[row][2kp], W[row][2kp+1]}.
__device__ __forceinline__ void gemm64g(ull acc[JP][2][2], const ull* __restrict__ w,
                                        const ull* __restrict__ hb, int rowoff)
{
    #pragma unroll 4
    for (int kq = 0; kq < 16; kq++){
        const int kp0 = 2 * kq;
        const ull* wr0 = w + kp0 * 256 + rowoff;   // k-pair kp0
        const ull* wr1 = wr0 + 256;                // k-pair kp0+1
        ulonglong2 a0 = *(const ulonglong2*)(wr0);       // gate A, ch {0,1}
        ulonglong2 b0 = *(const ulonglong2*)(wr0 + 64);  // gate B
        ulonglong2 a1 = *(const ulonglong2*)(wr1);
        ulonglong2 b1 = *(const ulonglong2*)(wr1 + 64);
        #pragma unroll
        for (int j = 0; j < JP; j++){
            ulonglong2 hv = *(const ulonglong2*)(hb + j * 32 + kp0);  // broadcast
            fma2(acc[j][0][0], hv.x, a0.x); fma2(acc[j][0][1], hv.x, a0.y);
            fma2(acc[j][1][0], hv.x, b0.x); fma2(acc[j][1][1], hv.x, b0.y);
            fma2(acc[j][0][0], hv.y, a1.x); fma2(acc[j][0][1], hv.y, a1.y);
            fma2(acc[j][1][0], hv.y, b1.x); fma2(acc[j][1][1], hv.y, b1.y);
        }
    }
}

__global__ void __launch_bounds__(NTHREADS, 1)
lstm_forecaster_kernel(const float* __restrict__ x,
                       const float* __restrict__ W_ih0, const float* __restrict__ W_hh0,
                       const float* __restrict__ b_ih0, const float* __restrict__ b_hh0,
                       const float* __restrict__ W_ih1, const float* __restrict__ W_hh1,
                       const float* __restrict__ b_ih1, const float* __restrict__ b_hh1,
                       const float* __restrict__ W_fc,  const float* __restrict__ b_fc,
                       float* __restrict__ out)
{
    ull* w0 = smem + W0_ULL;
    ull* wc = smem + WC_ULL;

    const int tid    = threadIdx.x;
    const int hp     = tid & 31;          // lane: owns gate-channels {2hp, 2hp+1}
    const int wid    = tid >> 5;
    const int pairid = wid & 3;
    const int m      = wid >> 2;          // 0: gates {i,f}; 1: gates {g,o}
    const int rowoff = m * 128 + 2 * hp;
    const int gb0    = blockIdx.x * NB + pairid * JP;
    const int barid  = pairid + 1;

    ull* h0p  = smem + HB_ULL  + pairid * (2 * JP * 32);   // [8][32]
    ull* h1p  = h0p + JP * 32;
    ull* padp = smem + PAD_ULL + pairid * (JP * 2 * 32);   // [8][2][32]

    // ---- build k-pair-packed weight tiles ----
    for (int i = tid; i < 32 * 256; i += NTHREADS){
        int kp = i >> 8, row = i & 255;
        w0[i] = pack2(W_hh0[row * H + 2*kp], W_hh0[row * H + 2*kp + 1]);
    }
    for (int i = tid; i < 64 * 256; i += NTHREADS){
        int kp = i >> 8, row = i & 255;
        const float* Ws = (kp < 32) ? W_ih1 : W_hh1;
        int kk = (kp & 31) * 2;
        wc[i] = pack2(Ws[row * H + kk], Ws[row * H + kk + 1]);
    }
    for (int i = tid; i < NPAIRS * 2 * JP * 32; i += NTHREADS) smem[HB_ULL + i] = 0ull;

    // ---- per-lane constants (all 4 gates; rows g*64+2hp, +1) ----
    float bias0[4][2], bias1[4][2], wih0r[4][2];
    #pragma unroll
    for (int g = 0; g < 4; g++){
        int ra = g * 64 + 2 * hp, rb = ra + 1;
        bias0[g][0] = b_ih0[ra] + b_hh0[ra];  bias0[g][1] = b_ih0[rb] + b_hh0[rb];
        bias1[g][0] = b_ih1[ra] + b_hh1[ra];  bias1[g][1] = b_ih1[rb] + b_hh1[rb];
        wih0r[g][0] = W_ih0[ra];              wih0r[g][1] = W_ih0[rb];
    }
    const float wfc0 = W_fc[2 * hp], wfc1 = W_fc[2 * hp + 1];

    float c0[JO][2], c1[JO][2];   // c-state only for owned batches
    #pragma unroll
    for (int jj = 0; jj < JO; jj++){
        c0[jj][0] = c0[jj][1] = 0.0f;
        c1[jj][0] = c1[jj][1] = 0.0f;
    }

    __syncthreads();

    #define PAIR_BAR() asm volatile("bar.sync %0, 64;" :: "r"(barid) : "memory")

    for (int t = 0; t < T_STEPS; t++){
        // x for owned batches
        float xv[JO];
        #pragma unroll
        for (int jj = 0; jj < JO; jj++)
            xv[jj] = __ldg(&x[(gb0 + m * JO + jj) * T_STEPS + t]);

        ull acc[JP][2][2];

        // ================= layer 0 =================
        #pragma unroll
        for (int j = 0; j < JP; j++){
            acc[j][0][0] = acc[j][0][1] = 0ull;
            acc[j][1][0] = acc[j][1][1] = 0ull;
        }
        gemm64g(acc, w0, h0p, rowoff);

        // ship this member's 2 gates for the 4 NON-owned batches
        #pragma unroll
        for (int jj = 0; jj < JO; jj++){
            int j = (1 - m) * JO + jj;
            padp[j * 64 + hp]      = pack2(sum2(acc[j][0][0]), sum2(acc[j][0][1]));
            padp[j * 64 + 32 + hp] = pack2(sum2(acc[j][1][0]), sum2(acc[j][1][1]));
        }
        PAIR_BAR();

        // update owned batches: own gates from regs, partner gates from pad
        #pragma unroll
        for (int jj = 0; jj < JO; jj++){
            int j = m * JO + jj;
            float a00 = sum2(acc[j][0][0]), a01 = sum2(acc[j][0][1]);
            float a10 = sum2(acc[j][1][0]), a11 = sum2(acc[j][1][1]);
            float2 p0 = unpack2(padp[j * 64 + hp]);
            float2 p1 = unpack2(padp[j * 64 + 32 + hp]);
            float vi0, vi1, vf0, vf1, vg0, vg1, vo0, vo1;
            if (m == 0){ vi0=a00; vi1=a01; vf0=a10; vf1=a11;
                         vg0=p0.x; vg1=p0.y; vo0=p1.x; vo1=p1.y; }
            else       { vi0=p0.x; vi1=p0.y; vf0=p1.x; vf1=p1.y;
                         vg0=a00; vg1=a01; vo0=a10; vo1=a11; }
            vi0 += fmaf(xv[jj], wih0r[0][0], bias0[0][0]);
            vi1 += fmaf(xv[jj], wih0r[0][1], bias0[0][1]);
            vf0 += fmaf(xv[jj], wih0r[1][0], bias0[1][0]);
            vf1 += fmaf(xv[jj], wih0r[1][1], bias0[1][1]);
            vg0 += fmaf(xv[jj], wih0r[2][0], bias0[2][0]);
            vg1 += fmaf(xv[jj], wih0r[2][1], bias0[2][1]);
            vo0 += fmaf(xv[jj], wih0r[3][0], bias0[3][0]);
            vo1 += fmaf(xv[jj], wih0r[3][1], bias0[3][1]);
            float ccx = sigm(vf0) * c0[jj][0] + sigm(vi0) * tanh_f(vg0);
            float ccy = sigm(vf1) * c0[jj][1] + sigm(vi1) * tanh_f(vg1);
            c0[jj][0] = ccx; c0[jj][1] = ccy;
            h0p[j * 32 + hp] = pack2(sigm(vo0) * tanh_f(ccx), sigm(vo1) * tanh_f(ccy));
        }
        PAIR_BAR();

        // ================= layer 1 =================
        #pragma unroll
        for (int j = 0; j < JP; j++){
            acc[j][0][0] = acc[j][0][1] = 0ull;
            acc[j][1][0] = acc[j][1][1] = 0ull;
        }
        gemm64g(acc, wc,            h0p, rowoff);   // W_ih1 * h0[t]
        gemm64g(acc, wc + 32 * 256, h1p, rowoff);   // W_hh1 * h1[t-1]

        #pragma unroll
        for (int jj = 0; jj < JO; jj++){
            int j = (1 - m) * JO + jj;
            padp[j * 64 + hp]      = pack2(sum2(acc[j][0][0]), sum2(acc[j][0][1]));
            padp[j * 64 + 32 + hp] = pack2(sum2(acc[j][1][0]), sum2(acc[j][1][1]));
        }
        PAIR_BAR();

        #pragma unroll
        for (int jj = 0; jj < JO; jj++){
            int j = m * JO + jj;
            float a00 = sum2(acc[j][0][0]), a01 = sum2(acc[j][0][1]);
            float a10 = sum2(acc[j][1][0]), a11 = sum2(acc[j][1][1]);
            float2 p0 = unpack2(padp[j * 64 + hp]);
            float2 p1 = unpack2(padp[j * 64 + 32 + hp]);
            float vi0, vi1, vf0, vf1, vg0, vg1, vo0, vo1;
            if (m == 0){ vi0=a00; vi1=a01; vf0=a10; vf1=a11;
                         vg0=p0.x; vg1=p0.y; vo0=p1.x; vo1=p1.y; }
            else       { vi0=p0.x; vi1=p0.y; vf0=p1.x; vf1=p1.y;
                         vg0=a00; vg1=a01; vo0=a10; vo1=a11; }
            vi0 += bias1[0][0]; vi1 += bias1[0][1];
            vf0 += bias1[1][0]; vf1 += bias1[1][1];
            vg0 += bias1[2][0]; vg1 += bias1[2][1];
            vo0 += bias1[3][0]; vo1 += bias1[3][1];
            float ccx = sigm(vf0) * c1[jj][0] + sigm(vi0) * tanh_f(vg0);
            float ccy = sigm(vf1) * c1[jj][1] + sigm(vi1) * tanh_f(vg1);
            c1[jj][0] = ccx; c1[jj][1] = ccy;
            h1p[j * 32 + hp] = pack2(sigm(vo0) * tanh_f(ccx), sigm(vo1) * tanh_f(ccy));
        }
        PAIR_BAR();
    }

    // ---- final FC on h1[T-1]: each member handles its owned batches ----
    #pragma unroll
    for (int jj = 0; jj < JO; jj++){
        int j = m * JO + jj;
        float2 h2 = unpack2(h1p[j * 32 + hp]);
        float s = h2.x * wfc0 + h2.y * wfc1;
        #pragma unroll
        for (int off = 16; off > 0; off >>= 1)
            s += __shfl_xor_sync(0xFFFFFFFFu, s, off);
        if (hp == 0) out[gb0 + j] = s + b_fc[0];
    }
}

extern "C" void kernel_launch(void* const* d_in, const int* in_sizes, int n_in,
                              void* d_out, int out_size)
{
    const float* x     = (const float*)d_in[0];
    const float* W_ih0 = (const float*)d_in[1];
    const float* W_hh0 = (const float*)d_in[2];
    const float* b_ih0 = (const float*)d_in[3];
    const float* b_hh0 = (const float*)d_in[4];
    const float* W_ih1 = (const float*)d_in[5];
    const float* W_hh1 = (const float*)d_in[6];
    const float* b_ih1 = (const float*)d_in[7];
    const float* b_hh1 = (const float*)d_in[8];
    const float* W_fc  = (const float*)d_in[9];
    const float* b_fc  = (const float*)d_in[10];
    float* out = (float*)d_out;

    cudaFuncSetAttribute(lstm_forecaster_kernel,
                         cudaFuncAttributeMaxDynamicSharedMemorySize, SMEM_BYTES);
    lstm_forecaster_kernel<<<B_TOTAL / NB, NTHREADS, SMEM_BYTES>>>(
        x, W_ih0, W_hh0, b_ih0, b_hh0,
        W_ih1, W_hh1, b_ih1, b_hh1, W_fc, b_fc, out);
}

// round 12
// speedup vs baseline: 2.3023x; 2.3023x over previous
#include <cuda_runtime.h>

typedef unsigned long long ull;

#define B_TOTAL  4096
#define T_STEPS  512
#define H        64
#define NTHREADS 256     // 8 warps = 4 pairs; pair = {w, w+4}
#define NPAIRS   4
#define JP       8       // batches per pair
#define JO       4       // batches owned (updated) per member warp
#define NB       32      // batches per CTA

// smem layout in ull (8B) units:
//   w0  [32][256] : w0[kp][row] = {W_hh0[row][2kp], W_hh0[row][2kp+1]}   64 KB
//   wc  [64][256] : kp<32 -> W_ih1 pairs, kp>=32 -> W_hh1 pairs         128 KB
//   hb  : per pair: h0[8][32] ull then h1[8][32] ull                     16 KB
//   pad : per pair: [8 batch][2 shipper-gates][32 lanes] ull partials    16 KB
#define W0_ULL   0
#define WC_ULL   (32*256)
#define HB_ULL   (WC_ULL + 64*256)           // 24576
#define PAD_ULL  (HB_ULL + NPAIRS*2*JP*32)   // 26624
#define SMEM_ULLS (PAD_ULL + NPAIRS*JP*2*32) // 28672
#define SMEM_BYTES (SMEM_ULLS * 8)           // 229376 <= 232448

__device__ __forceinline__ ull pack2(float a, float b){
    ull r; asm("mov.b64 %0, {%1, %2};" : "=l"(r) : "f"(a), "f"(b)); return r;
}
__device__ __forceinline__ void fma2(ull &d, ull a, ull b){
    asm("fma.rn.f32x2 %0, %1, %2, %0;" : "+l"(d) : "l"(a), "l"(b));
}
__device__ __forceinline__ float2 unpack2(ull v){
    float lo, hi; asm("mov.b64 {%0, %1}, %2;" : "=f"(lo), "=f"(hi) : "l"(v));
    return make_float2(lo, hi);
}
__device__ __forceinline__ float sum2(ull v){
    float2 p = unpack2(v); return p.x + p.y;
}
__device__ __forceinline__ float sigm(float x){
    float e = __expf(-fabsf(x));
    float s = __fdividef(1.0f, 1.0f + e);
    return (x >= 0.0f) ? s : 1.0f - s;
}
__device__ __forceinline__ float tanh_f(float x){
    float e = __expf(-2.0f * fabsf(x));
    float t = __fdividef(1.0f - e, 1.0f + e);
    return copysignf(t, x);
}

extern __shared__ ull smem[];

// Gate-split GEMM over a 64-deep K block. This member computes ONLY its two
// gate blocks (rows rowoff + {0,64} per k-pair) for all JP batches.
// Slot mapping: acc slots 0..JO-1 use h_own (owned batches), JO..JP-1 use
// h_oth — the (j<JO) select is COMPILE-TIME under full unroll, so all
// register-array indices are static (no spills).
__device__ __forceinline__ void gemm64g(ull acc[JP][2][2], const ull* __restrict__ w,
                                        const ull* __restrict__ h_own,
                                        const ull* __restrict__ h_oth, int rowoff)
{
    #pragma unroll 4
    for (int kq = 0; kq < 16; kq++){
        const int kp0 = 2 * kq;
        const ull* wr0 = w + kp0 * 256 + rowoff;   // k-pair kp0
        const ull* wr1 = wr0 + 256;                // k-pair kp0+1
        ulonglong2 a0 = *(const ulonglong2*)(wr0);       // gate A, ch {2hp,2hp+1}
        ulonglong2 b0 = *(const ulonglong2*)(wr0 + 64);  // gate B
        ulonglong2 a1 = *(const ulonglong2*)(wr1);
        ulonglong2 b1 = *(const ulonglong2*)(wr1 + 64);
        #pragma unroll
        for (int j = 0; j < JP; j++){
            const ull* hb = (j < JO) ? (h_own + j * 32) : (h_oth + (j - JO) * 32);
            ulonglong2 hv = *(const ulonglong2*)(hb + kp0);  // broadcast
            fma2(acc[j][0][0], hv.x, a0.x); fma2(acc[j][0][1], hv.x, a0.y);
            fma2(acc[j][1][0], hv.x, b0.x); fma2(acc[j][1][1], hv.x, b0.y);
            fma2(acc[j][0][0], hv.y, a1.x); fma2(acc[j][0][1], hv.y, a1.y);
            fma2(acc[j][1][0], hv.y, b1.x); fma2(acc[j][1][1], hv.y, b1.y);
        }
    }
}

__global__ void __launch_bounds__(NTHREADS, 1)
lstm_forecaster_kernel(const float* __restrict__ x,
                       const float* __restrict__ W_ih0, const float* __restrict__ W_hh0,
                       const float* __restrict__ b_ih0, const float* __restrict__ b_hh0,
                       const float* __restrict__ W_ih1, const float* __restrict__ W_hh1,
                       const float* __restrict__ b_ih1, const float* __restrict__ b_hh1,
                       const float* __restrict__ W_fc,  const float* __restrict__ b_fc,
                       float* __restrict__ out)
{
    ull* w0 = smem + W0_ULL;
    ull* wc = smem + WC_ULL;

    const int tid    = threadIdx.x;
    const int hp     = tid & 31;          // lane: owns gate-channels {2hp, 2hp+1}
    const int wid    = tid >> 5;
    const int pairid = wid & 3;
    const int m      = wid >> 2;          // 0: computes gates {i,f}; 1: gates {g,o}
    const int rowoff = m * 128 + 2 * hp;
    const int gb0    = blockIdx.x * NB + pairid * JP;
    const int gbo    = gb0 + m * JO;      // first OWNED global batch
    const int barid  = pairid + 1;

    ull* h0p  = smem + HB_ULL  + pairid * (2 * JP * 32);   // [8][32]
    ull* h1p  = h0p + JP * 32;
    ull* padp = smem + PAD_ULL + pairid * (JP * 2 * 32);   // [8][2][32]

    // runtime-offset views; register-array indices stay static
    const ull* h0_own = h0p + m * JO * 32;
    const ull* h0_oth = h0p + (1 - m) * JO * 32;
    const ull* h1_own = h1p + m * JO * 32;
    const ull* h1_oth = h1p + (1 - m) * JO * 32;
    ull* h0_wr = h0p + m * JO * 32;
    ull* h1_wr = h1p + m * JO * 32;
    ull* pad_ship = padp + (1 - m) * JO * 64;   // partner-owned batches
    ull* pad_read = padp + m * JO * 64;         // own batches (partner wrote)

    // ---- build k-pair-packed weight tiles ----
    for (int i = tid; i < 32 * 256; i += NTHREADS){
        int kp = i >> 8, row = i & 255;
        w0[i] = pack2(W_hh0[row * H + 2*kp], W_hh0[row * H + 2*kp + 1]);
    }
    for (int i = tid; i < 64 * 256; i += NTHREADS){
        int kp = i >> 8, row = i & 255;
        const float* Ws = (kp < 32) ? W_ih1 : W_hh1;
        int kk = (kp & 31) * 2;
        wc[i] = pack2(Ws[row * H + kk], Ws[row * H + kk + 1]);
    }
    for (int i = tid; i < NPAIRS * 2 * JP * 32; i += NTHREADS) smem[HB_ULL + i] = 0ull;

    // ---- per-lane constants (all 4 gates; rows g*64+2hp, +1) ----
    float bias0[4][2], bias1[4][2], wih0r[4][2];
    #pragma unroll
    for (int g = 0; g < 4; g++){
        int ra = g * 64 + 2 * hp, rb = ra + 1;
        bias0[g][0] = b_ih0[ra] + b_hh0[ra];  bias0[g][1] = b_ih0[rb] + b_hh0[rb];
        bias1[g][0] = b_ih1[ra] + b_hh1[ra];  bias1[g][1] = b_ih1[rb] + b_hh1[rb];
        wih0r[g][0] = W_ih0[ra];              wih0r[g][1] = W_ih0[rb];
    }
    const float wfc0 = W_fc[2 * hp], wfc1 = W_fc[2 * hp + 1];
    const bool mif = (m == 0);   // this member's own acc holds {i,f}

    float c0[JO][2], c1[JO][2];
    #pragma unroll
    for (int jj = 0; jj < JO; jj++){
        c0[jj][0] = c0[jj][1] = 0.0f;
        c1[jj][0] = c1[jj][1] = 0.0f;
    }

    __syncthreads();

    #define PAIR_BAR() asm volatile("bar.sync %0, 64;" :: "r"(barid) : "memory")

    for (int t = 0; t < T_STEPS; t++){
        float xv[JO];
        #pragma unroll
        for (int jj = 0; jj < JO; jj++)
            xv[jj] = __ldg(&x[(gbo + jj) * T_STEPS + t]);

        ull acc[JP][2][2];

        // ================= layer 0 =================
        #pragma unroll
        for (int j = 0; j < JP; j++){
            acc[j][0][0] = acc[j][0][1] = 0ull;
            acc[j][1][0] = acc[j][1][1] = 0ull;
        }
        gemm64g(acc, w0, h0_own, h0_oth, rowoff);

        // ship this member's 2 gate partials for partner-owned batches
        // (acc slots JO..JP-1; all indices static)
        #pragma unroll
        for (int jj = 0; jj < JO; jj++){
            pad_ship[jj * 64 + hp]      = pack2(sum2(acc[JO+jj][0][0]), sum2(acc[JO+jj][0][1]));
            pad_ship[jj * 64 + 32 + hp] = pack2(sum2(acc[JO+jj][1][0]), sum2(acc[JO+jj][1][1]));
        }
        PAIR_BAR();

        // update owned batches (acc slots 0..JO-1; partner gates from pad)
        #pragma unroll
        for (int jj = 0; jj < JO; jj++){
            float a00 = sum2(acc[jj][0][0]), a01 = sum2(acc[jj][0][1]);
            float a10 = sum2(acc[jj][1][0]), a11 = sum2(acc[jj][1][1]);
            float2 p0 = unpack2(pad_read[jj * 64 + hp]);
            float2 p1 = unpack2(pad_read[jj * 64 + 32 + hp]);
            float vi0 = mif ? a00 : p0.x,  vi1 = mif ? a01 : p0.y;
            float vf0 = mif ? a10 : p1.x,  vf1 = mif ? a11 : p1.y;
            float vg0 = mif ? p0.x : a00,  vg1 = mif ? p0.y : a01;
            float vo0 = mif ? p1.x : a10,  vo1 = mif ? p1.y : a11;
            vi0 += fmaf(xv[jj], wih0r[0][0], bias0[0][0]);
            vi1 += fmaf(xv[jj], wih0r[0][1], bias0[0][1]);
            vf0 += fmaf(xv[jj], wih0r[1][0], bias0[1][0]);
            vf1 += fmaf(xv[jj], wih0r[1][1], bias0[1][1]);
            vg0 += fmaf(xv[jj], wih0r[2][0], bias0[2][0]);
            vg1 += fmaf(xv[jj], wih0r[2][1], bias0[2][1]);
            vo0 += fmaf(xv[jj], wih0r[3][0], bias0[3][0]);
            vo1 += fmaf(xv[jj], wih0r[3][1], bias0[3][1]);
            float ccx = sigm(vf0) * c0[jj][0] + sigm(vi0) * tanh_f(vg0);
            float ccy = sigm(vf1) * c0[jj][1] + sigm(vi1) * tanh_f(vg1);
            c0[jj][0] = ccx; c0[jj][1] = ccy;
            h0_wr[jj * 32 + hp] = pack2(sigm(vo0) * tanh_f(ccx), sigm(vo1) * tanh_f(ccy));
        }
        PAIR_BAR();

        // ================= layer 1 =================
        #pragma unroll
        for (int j = 0; j < JP; j++){
            acc[j][0][0] = acc[j][0][1] = 0ull;
            acc[j][1][0] = acc[j][1][1] = 0ull;
        }
        gemm64g(acc, wc,            h0_own, h0_oth, rowoff);   // W_ih1 * h0[t]
        gemm64g(acc, wc + 32 * 256, h1_own, h1_oth, rowoff);   // W_hh1 * h1[t-1]

        #pragma unroll
        for (int jj = 0; jj < JO; jj++){
            pad_ship[jj * 64 + hp]      = pack2(sum2(acc[JO+jj][0][0]), sum2(acc[JO+jj][0][1]));
            pad_ship[jj * 64 + 32 + hp] = pack2(sum2(acc[JO+jj][1][0]), sum2(acc[JO+jj][1][1]));
        }
        PAIR_BAR();

        #pragma unroll
        for (int jj = 0; jj < JO; jj++){
            float a00 = sum2(acc[jj][0][0]), a01 = sum2(acc[jj][0][1]);
            float a10 = sum2(acc[jj][1][0]), a11 = sum2(acc[jj][1][1]);
            float2 p0 = unpack2(pad_read[jj * 64 + hp]);
            float2 p1 = unpack2(pad_read[jj * 64 + 32 + hp]);
            float vi0 = mif ? a00 : p0.x,  vi1 = mif ? a01 : p0.y;
            float vf0 = mif ? a10 : p1.x,  vf1 = mif ? a11 : p1.y;
            float vg0 = mif ? p0.x : a00,  vg1 = mif ? p0.y : a01;
            float vo0 = mif ? p1.x : a10,  vo1 = mif ? p1.y : a11;
            vi0 += bias1[0][0]; vi1 += bias1[0][1];
            vf0 += bias1[1][0]; vf1 += bias1[1][1];
            vg0 += bias1[2][0]; vg1 += bias1[2][1];
            vo0 += bias1[3][0]; vo1 += bias1[3][1];
            float ccx = sigm(vf0) * c1[jj][0] + sigm(vi0) * tanh_f(vg0);
            float ccy = sigm(vf1) * c1[jj][1] + sigm(vi1) * tanh_f(vg1);
            c1[jj][0] = ccx; c1[jj][1] = ccy;
            h1_wr[jj * 32 + hp] = pack2(sigm(vo0) * tanh_f(ccx), sigm(vo1) * tanh_f(ccy));
        }
        PAIR_BAR();
    }

    // ---- final FC on h1[T-1]: each member handles its owned batches ----
    #pragma unroll
    for (int jj = 0; jj < JO; jj++){
        float2 h2 = unpack2(h1_wr[jj * 32 + hp]);
        float s = h2.x * wfc0 + h2.y * wfc1;
        #pragma unroll
        for (int off = 16; off > 0; off >>= 1)
            s += __shfl_xor_sync(0xFFFFFFFFu, s, off);
        if (hp == 0) out[gbo + jj] = s + b_fc[0];
    }
}

extern "C" void kernel_launch(void* const* d_in, const int* in_sizes, int n_in,
                              void* d_out, int out_size)
{
    const float* x     = (const float*)d_in[0];
    const float* W_ih0 = (const float*)d_in[1];
    const float* W_hh0 = (const float*)d_in[2];
    const float* b_ih0 = (const float*)d_in[3];
    const float* b_hh0 = (const float*)d_in[4];
    const float* W_ih1 = (const float*)d_in[5];
    const float* W_hh1 = (const float*)d_in[6];
    const float* b_ih1 = (const float*)d_in[7];
    const float* b_hh1 = (const float*)d_in[8];
    const float* W_fc  = (const float*)d_in[9];
    const float* b_fc  = (const float*)d_in[10];
    float* out = (float*)d_out;

    cudaFuncSetAttribute(lstm_forecaster_kernel,
                         cudaFuncAttributeMaxDynamicSharedMemorySize, SMEM_BYTES);
    lstm_forecaster_kernel<<<B_TOTAL / NB, NTHREADS, SMEM_BYTES>>>(
        x, W_ih0, W_hh0, b_ih0, b_hh0,
        W_ih1, W_hh1, b_ih1, b_hh1, W_fc, b_fc, out);
}